// round 4
// baseline (speedup 1.0000x reference)
#include <cuda_runtime.h>

#define NROWS   4096
#define S_SLOTS 200
#define X_DIM   64
#define M_DIM   364
#define O_DIM   64
#define F4      91                    // M_DIM / 4
#define EPS     1e-6f
#define NT      256
#define NW      8

#define SLOT_B      (M_DIM * 4)           // 1456 bytes per slot
#define STAGE_SLOTS 8
#define STAGE_F4    (STAGE_SLOTS * F4)    // 728 float4 per stage
#define STAGE_B     (STAGE_SLOTS * SLOT_B) // 11648 bytes per stage
#define NSTAGES     (S_SLOTS / STAGE_SLOTS) // 25
#define DEPTH       3

__global__ __launch_bounds__(NT)
void mem_attn_kernel(const float* __restrict__ x,
                     const float* __restrict__ mem,
                     const float* __restrict__ W_x,
                     const float* __restrict__ b_x,
                     const float* __restrict__ W_out,
                     const float* __restrict__ b_out,
                     float* __restrict__ out)
{
    __shared__ __align__(16) char  sbuf[DEPTH * STAGE_B];   // 34944 B
    __shared__ __align__(16) float sh_h[M_DIM];
    __shared__ float sh_x[X_DIM];
    __shared__ float sh_red[NW];
    __shared__ float sh_wsum[NW];

    const int n    = blockIdx.x;
    const int t    = threadIdx.x;
    const int lane = t & 31;
    const int w    = t >> 5;

    const float* memn = mem + (size_t)n * S_SLOTS * M_DIM;

    // ---- kick off the first DEPTH stage copies immediately ----
    #pragma unroll
    for (int st = 0; st < DEPTH; st++) {
        const char* gsrc = (const char*)memn + (size_t)st * STAGE_B;
        unsigned sdst = (unsigned)__cvta_generic_to_shared(sbuf + st * STAGE_B);
        for (int j = t; j < STAGE_F4; j += NT) {
            asm volatile("cp.async.cg.shared.global [%0], [%1], 16;"
                         :: "r"(sdst + j * 16), "l"(gsrc + j * 16));
        }
        asm volatile("cp.async.commit_group;");
    }

    // ---- load x row, compute h = relu(x @ W_x + b_x) and ||h|| ----
    if (t < X_DIM) sh_x[t] = x[(size_t)n * X_DIM + t];
    __syncthreads();

    float hn_part = 0.f;
    for (int j = t; j < M_DIM; j += NT) {
        float a = b_x[j];
        #pragma unroll 16
        for (int i = 0; i < X_DIM; i++) a = fmaf(sh_x[i], W_x[i * M_DIM + j], a);
        a = fmaxf(a, 0.f);
        sh_h[j] = a;
        hn_part = fmaf(a, a, hn_part);
    }
    #pragma unroll
    for (int o = 16; o > 0; o >>= 1) hn_part += __shfl_xor_sync(0xffffffffu, hn_part, o);
    if (lane == 0) sh_red[w] = hn_part;
    __syncthreads();
    float hsum = 0.f;
    #pragma unroll
    for (int i = 0; i < NW; i++) hsum += sh_red[i];
    const float inv_hnorm = 1.f / fmaxf(sqrtf(hsum), EPS);

    const float4* sh_h4 = reinterpret_cast<const float4*>(sh_h);
    const bool has2 = (lane + 64) < F4;   // lanes 0..26
    const float4 h0 = sh_h4[lane];
    const float4 h1 = sh_h4[lane + 32];
    const float4 h2 = has2 ? sh_h4[lane + 64] : make_float4(0.f, 0.f, 0.f, 0.f);

    // ---- streamed mainloop: warp w computes slot (st*8 + w) of each stage ----
    float4 acc0 = make_float4(0.f, 0.f, 0.f, 0.f);
    float4 acc1 = make_float4(0.f, 0.f, 0.f, 0.f);
    float4 acc2 = make_float4(0.f, 0.f, 0.f, 0.f);
    float rsum = 0.f;

    for (int st = 0; st < NSTAGES; st++) {
        asm volatile("cp.async.wait_group 2;");   // stage st (oldest) complete
        __syncthreads();

        const float4* slot = reinterpret_cast<const float4*>(
            sbuf + (st % DEPTH) * STAGE_B + w * SLOT_B);
        float4 v0 = slot[lane];
        float4 v1 = slot[lane + 32];
        float4 v2 = has2 ? slot[lane + 64] : make_float4(0.f, 0.f, 0.f, 0.f);

        float dot = v0.x*h0.x + v0.y*h0.y + v0.z*h0.z + v0.w*h0.w
                  + v1.x*h1.x + v1.y*h1.y + v1.z*h1.z + v1.w*h1.w
                  + v2.x*h2.x + v2.y*h2.y + v2.z*h2.z + v2.w*h2.w;
        float nsq = v0.x*v0.x + v0.y*v0.y + v0.z*v0.z + v0.w*v0.w
                  + v1.x*v1.x + v1.y*v1.y + v1.z*v1.z + v1.w*v1.w
                  + v2.x*v2.x + v2.y*v2.y + v2.z*v2.z + v2.w*v2.w;
        #pragma unroll
        for (int o = 16; o > 0; o >>= 1) {
            dot += __shfl_xor_sync(0xffffffffu, dot, o);
            nsq += __shfl_xor_sync(0xffffffffu, nsq, o);
        }

        // cosine sim in [-1,1] -> exp() safe without max subtraction
        const float sim = dot * inv_hnorm / fmaxf(sqrtf(nsq), EPS);
        const float e = __expf(sim);
        rsum += e;

        acc0.x = fmaf(e, v0.x, acc0.x); acc0.y = fmaf(e, v0.y, acc0.y);
        acc0.z = fmaf(e, v0.z, acc0.z); acc0.w = fmaf(e, v0.w, acc0.w);
        acc1.x = fmaf(e, v1.x, acc1.x); acc1.y = fmaf(e, v1.y, acc1.y);
        acc1.z = fmaf(e, v1.z, acc1.z); acc1.w = fmaf(e, v1.w, acc1.w);
        acc2.x = fmaf(e, v2.x, acc2.x); acc2.y = fmaf(e, v2.y, acc2.y);
        acc2.z = fmaf(e, v2.z, acc2.z); acc2.w = fmaf(e, v2.w, acc2.w);

        __syncthreads();   // everyone done reading buffer (st % DEPTH)

        const int nst = st + DEPTH;
        if (nst < NSTAGES) {
            const char* gsrc = (const char*)memn + (size_t)nst * STAGE_B;
            unsigned sdst = (unsigned)__cvta_generic_to_shared(sbuf + (st % DEPTH) * STAGE_B);
            for (int j = t; j < STAGE_F4; j += NT) {
                asm volatile("cp.async.cg.shared.global [%0], [%1], 16;"
                             :: "r"(sdst + j * 16), "l"(gsrc + j * 16));
            }
        }
        asm volatile("cp.async.commit_group;");   // empty groups keep count consistent
    }

    // ---- merge warps; reuse retired stage buffers as scratch ----
    float* accbuf = reinterpret_cast<float*>(sbuf);                 // [NW][M_DIM]
    float* g      = reinterpret_cast<float*>(sbuf + STAGE_B);       // [M_DIM]
    float (*outb)[O_DIM] = reinterpret_cast<float (*)[O_DIM]>(sbuf + 2 * STAGE_B);

    if (lane == 0) sh_wsum[w] = rsum;
    {
        float4* dst = reinterpret_cast<float4*>(accbuf + w * M_DIM);
        dst[lane]      = acc0;
        dst[lane + 32] = acc1;
        if (has2) dst[lane + 64] = acc2;
    }
    __syncthreads();

    float total = 0.f;
    #pragma unroll
    for (int i = 0; i < NW; i++) total += sh_wsum[i];

    const float inv = 1.f / (total * (float)S_SLOTS);
    for (int j = t; j < M_DIM; j += NT) {
        float p = 0.f;
        #pragma unroll
        for (int i = 0; i < NW; i++) p += accbuf[i * M_DIM + j];
        g[j] = p * inv * sh_h[j];
    }
    __syncthreads();

    // ---- out = relu((pooled*h) @ W_out + b_out) ----
    {
        const int oc = t & 63;
        const int c  = t >> 6;           // 4 chunks of 91
        float a = 0.f;
        const int m0 = c * F4;
        #pragma unroll 13
        for (int m = m0; m < m0 + F4; m++) a = fmaf(g[m], W_out[m * O_DIM + oc], a);
        outb[c][oc] = a;
    }
    __syncthreads();
    if (t < O_DIM) {
        float a = outb[0][t] + outb[1][t] + outb[2][t] + outb[3][t] + b_out[t];
        out[(size_t)n * O_DIM + t] = fmaxf(a, 0.f);
    }
}

extern "C" void kernel_launch(void* const* d_in, const int* in_sizes, int n_in,
                              void* d_out, int out_size)
{
    const float* x     = (const float*)d_in[0];
    const float* mem   = (const float*)d_in[1];
    const float* W_x   = (const float*)d_in[2];
    const float* b_x   = (const float*)d_in[3];
    const float* W_out = (const float*)d_in[4];
    const float* b_out = (const float*)d_in[5];
    float* out = (float*)d_out;

    mem_attn_kernel<<<NROWS, NT>>>(x, mem, W_x, b_x, W_out, b_out, out);
}

// round 5
// speedup vs baseline: 1.0668x; 1.0668x over previous
#include <cuda_runtime.h>

#define NROWS   4096
#define S_SLOTS 200
#define X_DIM   64
#define M_DIM   364
#define O_DIM   64
#define F4      91                    // M_DIM / 4
#define EPS     1e-6f
#define NT      256
#define NW      8
#define SLOT_B  (M_DIM * 4)           // 1456 bytes per slot
#define DEPTH   4
#define SPW     (S_SLOTS / NW)        // 25 slots per warp

__global__ __launch_bounds__(NT)
void mem_attn_kernel(const float* __restrict__ x,
                     const float* __restrict__ mem,
                     const float* __restrict__ W_x,
                     const float* __restrict__ b_x,
                     const float* __restrict__ W_out,
                     const float* __restrict__ b_out,
                     float* __restrict__ out)
{
    // per-warp private ring buffers: warp w owns sbuf[w][0..DEPTH)
    __shared__ __align__(16) char  sbuf[NW][DEPTH][SLOT_B];  // 46592 B
    __shared__ __align__(16) float sh_h[M_DIM];
    __shared__ float sh_x[X_DIM];
    __shared__ float sh_red[NW];
    __shared__ float sh_wsum[NW];

    const int n    = blockIdx.x;
    const int t    = threadIdx.x;
    const int lane = t & 31;
    const int w    = t >> 5;

    const float* memn = mem + (size_t)n * S_SLOTS * M_DIM;
    const bool has2   = lane < (F4 - 64);          // lanes 0..26
    const int  off0   = lane * 16;                 // byte offsets within slot
    const int  off1   = off0 + 512;
    const int  off2   = off0 + 1024;

    const unsigned swarp = (unsigned)__cvta_generic_to_shared(&sbuf[w][0][0]);

    // ---- prologue: fill this warp's ring (slots w, w+8, w+16, w+24) ----
    #pragma unroll
    for (int d = 0; d < DEPTH; d++) {
        const char* g = (const char*)(memn + (size_t)(w + NW * d) * M_DIM);
        const unsigned s = swarp + d * SLOT_B;
        asm volatile("cp.async.cg.shared.global [%0], [%1], 16;" :: "r"(s + off0), "l"(g + off0));
        asm volatile("cp.async.cg.shared.global [%0], [%1], 16;" :: "r"(s + off1), "l"(g + off1));
        if (has2)
            asm volatile("cp.async.cg.shared.global [%0], [%1], 16;" :: "r"(s + off2), "l"(g + off2));
        asm volatile("cp.async.commit_group;");
    }

    // ---- h = relu(x @ W_x + b_x) and 1/||h||  (overlaps prologue copies) ----
    if (t < X_DIM) sh_x[t] = x[(size_t)n * X_DIM + t];
    __syncthreads();

    float hn_part = 0.f;
    for (int j = t; j < M_DIM; j += NT) {
        float a = b_x[j];
        #pragma unroll 16
        for (int i = 0; i < X_DIM; i++) a = fmaf(sh_x[i], W_x[i * M_DIM + j], a);
        a = fmaxf(a, 0.f);
        sh_h[j] = a;
        hn_part = fmaf(a, a, hn_part);
    }
    #pragma unroll
    for (int o = 16; o > 0; o >>= 1) hn_part += __shfl_xor_sync(0xffffffffu, hn_part, o);
    if (lane == 0) sh_red[w] = hn_part;
    __syncthreads();
    float hsum = 0.f;
    #pragma unroll
    for (int i = 0; i < NW; i++) hsum += sh_red[i];
    const float inv_hnorm = 1.f / fmaxf(sqrtf(hsum), EPS);

    const float4* sh_h4 = reinterpret_cast<const float4*>(sh_h);
    const float4 h0 = sh_h4[lane];
    const float4 h1 = sh_h4[lane + 32];
    const float4 h2 = has2 ? sh_h4[lane + 64] : make_float4(0.f, 0.f, 0.f, 0.f);

    // ---- barrier-free mainloop: each warp streams its own 25 slots ----
    float4 acc0 = make_float4(0.f, 0.f, 0.f, 0.f);
    float4 acc1 = make_float4(0.f, 0.f, 0.f, 0.f);
    float4 acc2 = make_float4(0.f, 0.f, 0.f, 0.f);
    float rsum = 0.f;

    for (int i = 0; i < SPW; i++) {
        asm volatile("cp.async.wait_group %0;" :: "n"(DEPTH - 1));
        // each lane reads exactly the float4s it copied -> per-thread
        // cp.async visibility suffices; no sync of any kind needed.
        const float4* slot = reinterpret_cast<const float4*>(&sbuf[w][i & (DEPTH - 1)][0]);
        float4 v0 = slot[lane];
        float4 v1 = slot[lane + 32];
        float4 v2 = has2 ? slot[lane + 64] : make_float4(0.f, 0.f, 0.f, 0.f);

        float dot = v0.x*h0.x + v0.y*h0.y + v0.z*h0.z + v0.w*h0.w
                  + v1.x*h1.x + v1.y*h1.y + v1.z*h1.z + v1.w*h1.w
                  + v2.x*h2.x + v2.y*h2.y + v2.z*h2.z + v2.w*h2.w;
        float nsq = v0.x*v0.x + v0.y*v0.y + v0.z*v0.z + v0.w*v0.w
                  + v1.x*v1.x + v1.y*v1.y + v1.z*v1.z + v1.w*v1.w
                  + v2.x*v2.x + v2.y*v2.y + v2.z*v2.z + v2.w*v2.w;
        #pragma unroll
        for (int o = 16; o > 0; o >>= 1) {
            dot += __shfl_xor_sync(0xffffffffu, dot, o);
            nsq += __shfl_xor_sync(0xffffffffu, nsq, o);
        }

        // cosine sim in [-1,1] -> exp() safe without max subtraction
        const float sim = dot * inv_hnorm / fmaxf(sqrtf(nsq), EPS);
        const float e = __expf(sim);
        rsum += e;

        acc0.x = fmaf(e, v0.x, acc0.x); acc0.y = fmaf(e, v0.y, acc0.y);
        acc0.z = fmaf(e, v0.z, acc0.z); acc0.w = fmaf(e, v0.w, acc0.w);
        acc1.x = fmaf(e, v1.x, acc1.x); acc1.y = fmaf(e, v1.y, acc1.y);
        acc1.z = fmaf(e, v1.z, acc1.z); acc1.w = fmaf(e, v1.w, acc1.w);
        acc2.x = fmaf(e, v2.x, acc2.x); acc2.y = fmaf(e, v2.y, acc2.y);
        acc2.z = fmaf(e, v2.z, acc2.z); acc2.w = fmaf(e, v2.w, acc2.w);

        // refill the buffer just consumed with slot i+DEPTH
        const int nxt = i + DEPTH;
        if (nxt < SPW) {
            const char* g = (const char*)(memn + (size_t)(w + NW * nxt) * M_DIM);
            const unsigned s = swarp + (i & (DEPTH - 1)) * SLOT_B;
            asm volatile("cp.async.cg.shared.global [%0], [%1], 16;" :: "r"(s + off0), "l"(g + off0));
            asm volatile("cp.async.cg.shared.global [%0], [%1], 16;" :: "r"(s + off1), "l"(g + off1));
            if (has2)
                asm volatile("cp.async.cg.shared.global [%0], [%1], 16;" :: "r"(s + off2), "l"(g + off2));
        }
        asm volatile("cp.async.commit_group;");  // empty groups keep the count uniform
    }

    // ---- merge warps; all pending groups are empty now, sbuf reusable ----
    float* accbuf = reinterpret_cast<float*>(sbuf);           // [NW][M_DIM]
    float* g      = accbuf + NW * M_DIM;                      // [M_DIM]
    float (*outb)[O_DIM] = reinterpret_cast<float (*)[O_DIM]>(g + M_DIM);

    if (lane == 0) sh_wsum[w] = rsum;
    __syncthreads();   // all warps done with their rings before scratch reuse
    {
        float4* dst = reinterpret_cast<float4*>(accbuf + w * M_DIM);
        dst[lane]      = acc0;
        dst[lane + 32] = acc1;
        if (has2) dst[lane + 64] = acc2;
    }
    __syncthreads();

    float total = 0.f;
    #pragma unroll
    for (int i = 0; i < NW; i++) total += sh_wsum[i];

    const float inv = 1.f / (total * (float)S_SLOTS);
    for (int j = t; j < M_DIM; j += NT) {
        float p = 0.f;
        #pragma unroll
        for (int i = 0; i < NW; i++) p += accbuf[i * M_DIM + j];
        g[j] = p * inv * sh_h[j];
    }
    __syncthreads();

    // ---- out = relu((pooled*h) @ W_out + b_out) ----
    {
        const int oc = t & 63;
        const int c  = t >> 6;           // 4 chunks of 91
        float a = 0.f;
        const int m0 = c * F4;
        #pragma unroll 13
        for (int m = m0; m < m0 + F4; m++) a = fmaf(g[m], W_out[m * O_DIM + oc], a);
        outb[c][oc] = a;
    }
    __syncthreads();
    if (t < O_DIM) {
        float a = outb[0][t] + outb[1][t] + outb[2][t] + outb[3][t] + b_out[t];
        out[(size_t)n * O_DIM + t] = fmaxf(a, 0.f);
    }
}

extern "C" void kernel_launch(void* const* d_in, const int* in_sizes, int n_in,
                              void* d_out, int out_size)
{
    const float* x     = (const float*)d_in[0];
    const float* mem   = (const float*)d_in[1];
    const float* W_x   = (const float*)d_in[2];
    const float* b_x   = (const float*)d_in[3];
    const float* W_out = (const float*)d_in[4];
    const float* b_out = (const float*)d_in[5];
    float* out = (float*)d_out;

    mem_attn_kernel<<<NROWS, NT>>>(x, mem, W_x, b_x, W_out, b_out, out);
}

// round 6
// speedup vs baseline: 1.0802x; 1.0126x over previous
#include <cuda_runtime.h>

#define NROWS   4096
#define S_SLOTS 200
#define X_DIM   64
#define M_DIM   364
#define O_DIM   64
#define F4      91                    // M_DIM / 4
#define EPS     1e-6f
#define NT      256
#define NW      8
#define SLOT_B  (M_DIM * 4)           // 1456 bytes per slot
#define DEPTH   3
#define SPW     (S_SLOTS / NW)        // 25 slots per warp

__global__ __launch_bounds__(NT, 5)
void mem_attn_kernel(const float* __restrict__ x,
                     const float* __restrict__ mem,
                     const float* __restrict__ W_x,
                     const float* __restrict__ b_x,
                     const float* __restrict__ W_out,
                     const float* __restrict__ b_out,
                     float* __restrict__ out)
{
    // per-warp private ring buffers: warp w owns sbuf[w][0..DEPTH)
    __shared__ __align__(16) char  sbuf[NW][DEPTH][SLOT_B];  // 34944 B
    __shared__ __align__(16) float sh_h[M_DIM];
    __shared__ float sh_x[X_DIM];
    __shared__ float sh_red[NW];
    __shared__ float sh_wsum[NW];

    const int n    = blockIdx.x;
    const int t    = threadIdx.x;
    const int lane = t & 31;
    const int w    = t >> 5;

    const float* memn = mem + (size_t)n * S_SLOTS * M_DIM;
    const bool has2   = lane < (F4 - 64);          // lanes 0..26
    const int  off0   = lane * 16;                 // byte offsets within slot
    const int  off1   = off0 + 512;
    const int  off2   = off0 + 1024;

    const unsigned swarp = (unsigned)__cvta_generic_to_shared(&sbuf[w][0][0]);

    // ---- prologue: fill this warp's ring (slots w, w+8, w+16) ----
    #pragma unroll
    for (int d = 0; d < DEPTH; d++) {
        const char* g = (const char*)(memn + (size_t)(w + NW * d) * M_DIM);
        const unsigned s = swarp + d * SLOT_B;
        asm volatile("cp.async.cg.shared.global [%0], [%1], 16;" :: "r"(s + off0), "l"(g + off0));
        asm volatile("cp.async.cg.shared.global [%0], [%1], 16;" :: "r"(s + off1), "l"(g + off1));
        if (has2)
            asm volatile("cp.async.cg.shared.global [%0], [%1], 16;" :: "r"(s + off2), "l"(g + off2));
        asm volatile("cp.async.commit_group;");
    }

    // ---- h = relu(x @ W_x + b_x) and 1/||h||  (overlaps prologue copies) ----
    if (t < X_DIM) sh_x[t] = x[(size_t)n * X_DIM + t];
    __syncthreads();

    float hn_part = 0.f;
    for (int j = t; j < M_DIM; j += NT) {
        float a = b_x[j];
        #pragma unroll 16
        for (int i = 0; i < X_DIM; i++) a = fmaf(sh_x[i], W_x[i * M_DIM + j], a);
        a = fmaxf(a, 0.f);
        sh_h[j] = a;
        hn_part = fmaf(a, a, hn_part);
    }
    #pragma unroll
    for (int o = 16; o > 0; o >>= 1) hn_part += __shfl_xor_sync(0xffffffffu, hn_part, o);
    if (lane == 0) sh_red[w] = hn_part;
    __syncthreads();
    float hsum = 0.f;
    #pragma unroll
    for (int i = 0; i < NW; i++) hsum += sh_red[i];
    const float inv_hnorm = 1.f / fmaxf(sqrtf(hsum), EPS);

    const float4* sh_h4 = reinterpret_cast<const float4*>(sh_h);

    // ---- barrier-free mainloop: each warp streams its own 25 slots.
    //      h is re-read from smem each slot to keep regs <= 51 (5 blocks/SM).
    float4 acc0 = make_float4(0.f, 0.f, 0.f, 0.f);
    float4 acc1 = make_float4(0.f, 0.f, 0.f, 0.f);
    float4 acc2 = make_float4(0.f, 0.f, 0.f, 0.f);
    float rsum = 0.f;

    int rb = 0;   // ring index = i % DEPTH
    for (int i = 0; i < SPW; i++) {
        asm volatile("cp.async.wait_group %0;" :: "n"(DEPTH - 1));
        // each lane reads exactly the float4s it copied -> per-thread
        // cp.async visibility suffices; no sync of any kind needed.
        const float4* slot = reinterpret_cast<const float4*>(&sbuf[w][rb][0]);
        float4 v0 = slot[lane];
        float4 v1 = slot[lane + 32];
        float4 v2 = has2 ? slot[lane + 64] : make_float4(0.f, 0.f, 0.f, 0.f);
        float4 h0 = sh_h4[lane];
        float4 h1 = sh_h4[lane + 32];
        float4 h2 = has2 ? sh_h4[lane + 64] : make_float4(0.f, 0.f, 0.f, 0.f);

        // EARLY refill: issue the next copy into this buffer before the
        // compute chain. The LDS results above complete in ~29cyc; the
        // cp.async smem write cannot arrive for >=300cyc (L2/DRAM RT), and
        // same-thread same-address ops issue in program order -> safe.
        const int nxt = i + DEPTH;
        if (nxt < SPW) {
            const char* g = (const char*)(memn + (size_t)(w + NW * nxt) * M_DIM);
            const unsigned s = swarp + rb * SLOT_B;
            asm volatile("cp.async.cg.shared.global [%0], [%1], 16;" :: "r"(s + off0), "l"(g + off0));
            asm volatile("cp.async.cg.shared.global [%0], [%1], 16;" :: "r"(s + off1), "l"(g + off1));
            if (has2)
                asm volatile("cp.async.cg.shared.global [%0], [%1], 16;" :: "r"(s + off2), "l"(g + off2));
        }
        asm volatile("cp.async.commit_group;");  // empty groups keep count uniform

        float dot = v0.x*h0.x + v0.y*h0.y + v0.z*h0.z + v0.w*h0.w
                  + v1.x*h1.x + v1.y*h1.y + v1.z*h1.z + v1.w*h1.w
                  + v2.x*h2.x + v2.y*h2.y + v2.z*h2.z + v2.w*h2.w;
        float nsq = v0.x*v0.x + v0.y*v0.y + v0.z*v0.z + v0.w*v0.w
                  + v1.x*v1.x + v1.y*v1.y + v1.z*v1.z + v1.w*v1.w
                  + v2.x*v2.x + v2.y*v2.y + v2.z*v2.z + v2.w*v2.w;
        #pragma unroll
        for (int o = 16; o > 0; o >>= 1) {
            dot += __shfl_xor_sync(0xffffffffu, dot, o);
            nsq += __shfl_xor_sync(0xffffffffu, nsq, o);
        }

        // cosine sim in [-1,1] -> exp() safe without max subtraction
        const float sim = dot * inv_hnorm / fmaxf(sqrtf(nsq), EPS);
        const float e = __expf(sim);
        rsum += e;

        acc0.x = fmaf(e, v0.x, acc0.x); acc0.y = fmaf(e, v0.y, acc0.y);
        acc0.z = fmaf(e, v0.z, acc0.z); acc0.w = fmaf(e, v0.w, acc0.w);
        acc1.x = fmaf(e, v1.x, acc1.x); acc1.y = fmaf(e, v1.y, acc1.y);
        acc1.z = fmaf(e, v1.z, acc1.z); acc1.w = fmaf(e, v1.w, acc1.w);
        acc2.x = fmaf(e, v2.x, acc2.x); acc2.y = fmaf(e, v2.y, acc2.y);
        acc2.z = fmaf(e, v2.z, acc2.z); acc2.w = fmaf(e, v2.w, acc2.w);

        rb = (rb == DEPTH - 1) ? 0 : rb + 1;
    }

    // ---- merge warps; all remaining groups are empty, data consumed ----
    float* accbuf = reinterpret_cast<float*>(sbuf);           // [NW][M_DIM]
    float* g      = accbuf + NW * M_DIM;                      // [M_DIM]
    float (*outb)[O_DIM] = reinterpret_cast<float (*)[O_DIM]>(g + M_DIM);

    if (lane == 0) sh_wsum[w] = rsum;
    __syncthreads();   // all warps done with their rings before scratch reuse
    {
        float4* dst = reinterpret_cast<float4*>(accbuf + w * M_DIM);
        dst[lane]      = acc0;
        dst[lane + 32] = acc1;
        if (has2) dst[lane + 64] = acc2;
    }
    __syncthreads();

    float total = 0.f;
    #pragma unroll
    for (int i = 0; i < NW; i++) total += sh_wsum[i];

    const float inv = 1.f / (total * (float)S_SLOTS);
    for (int j = t; j < M_DIM; j += NT) {
        float p = 0.f;
        #pragma unroll
        for (int i = 0; i < NW; i++) p += accbuf[i * M_DIM + j];
        g[j] = p * inv * sh_h[j];
    }
    __syncthreads();

    // ---- out = relu((pooled*h) @ W_out + b_out) ----
    {
        const int oc = t & 63;
        const int c  = t >> 6;           // 4 chunks of 91
        float a = 0.f;
        const int m0 = c * F4;
        #pragma unroll 13
        for (int m = m0; m < m0 + F4; m++) a = fmaf(g[m], W_out[m * O_DIM + oc], a);
        outb[c][oc] = a;
    }
    __syncthreads();
    if (t < O_DIM) {
        float a = outb[0][t] + outb[1][t] + outb[2][t] + outb[3][t] + b_out[t];
        out[(size_t)n * O_DIM + t] = fmaxf(a, 0.f);
    }
}

extern "C" void kernel_launch(void* const* d_in, const int* in_sizes, int n_in,
                              void* d_out, int out_size)
{
    const float* x     = (const float*)d_in[0];
    const float* mem   = (const float*)d_in[1];
    const float* W_x   = (const float*)d_in[2];
    const float* b_x   = (const float*)d_in[3];
    const float* W_out = (const float*)d_in[4];
    const float* b_out = (const float*)d_in[5];
    float* out = (float*)d_out;

    mem_attn_kernel<<<NROWS, NT>>>(x, mem, W_x, b_x, W_out, b_out, out);
}